// round 12
// baseline (speedup 1.0000x reference)
#include <cuda_runtime.h>
#include <math.h>

#define NN 200000
#define NE 3200000
#define NP 4096
#define SCAN_T 1024
#define SCAN_NB 196   // ceil(NN/1024)

// ---------------- scratch (__device__ globals; no allocation) ----------------
__device__ int d_deg[NN];            // invariant: zero at entry (restored by k_scan)
__device__ int d_start[NN];          // segment start per node (arrival-ordered)
__device__ int d_len[NN];            // segment length per node
__device__ int d_cursor[NN];
__device__ int d_gctr;               // global range allocator (zeroed by k_hist)
__device__ int d_ssrc[NE];           // src indices grouped by dst
__device__ float d_mean[NN * 32];    // per-layer aggregated mean scratch

// ---------------- CSR build: hist -> scan -> scatter (3 launches) ----------------
// int4-vectorized edge reads (NE % 4 == 0).
__global__ void k_hist(const int* __restrict__ dst) {
    if (blockIdx.x == 0 && threadIdx.x == 0) d_gctr = 0;   // consumed next launch
    int e = blockIdx.x * blockDim.x + threadIdx.x;
    if (e < NE / 4) {
        int4 d = ((const int4*)dst)[e];
        atomicAdd(&d_deg[d.x], 1);
        atomicAdd(&d_deg[d.y], 1);
        atomicAdd(&d_deg[d.z], 1);
        atomicAdd(&d_deg[d.w], 1);
    }
}

// Block-local inclusive scan + atomic block-range grab (arrival-ordered across
// blocks; valid since consumers only need disjoint start+len per node).
__global__ void k_scan() {
    __shared__ int s[SCAN_T];
    __shared__ int blockBase;
    int t = threadIdx.x;
    int i = blockIdx.x * SCAN_T + t;
    int v = (i < NN) ? d_deg[i] : 0;
    s[t] = v;
    __syncthreads();
    for (int o = 1; o < SCAN_T; o <<= 1) {
        int tv = (t >= o) ? s[t - o] : 0;
        __syncthreads();
        s[t] += tv;
        __syncthreads();
    }
    if (t == SCAN_T - 1) blockBase = atomicAdd(&d_gctr, s[SCAN_T - 1]);
    __syncthreads();
    if (i < NN) {
        int excl = blockBase + s[t] - v;
        d_start[i]  = excl;
        d_cursor[i] = excl;
        d_len[i]    = v;
        d_deg[i]    = 0;                 // restore zero invariant for next call
    }
}

__global__ void k_scatter(const int* __restrict__ src, const int* __restrict__ dst) {
    int e = blockIdx.x * blockDim.x + threadIdx.x;
    if (e < NE / 4) {
        int4 d = ((const int4*)dst)[e];
        int4 s = ((const int4*)src)[e];
        d_ssrc[atomicAdd(&d_cursor[d.x], 1)] = s.x;
        d_ssrc[atomicAdd(&d_cursor[d.y], 1)] = s.y;
        d_ssrc[atomicAdd(&d_cursor[d.z], 1)] = s.z;
        d_ssrc[atomicAdd(&d_cursor[d.w], 1)] = s.w;
    }
}

// ---------------- aggregation: mean of in-neighbors -> d_mean ----------------
// One warp per node (round-5 proven form). Lane = (edge-group l>>3, float4-chunk
// l&7); 4 edges per warp-iteration via LDG.128. STRIDE compile-time so row
// addressing is shift-based.
template <int STRIDE>
__global__ void __launch_bounds__(256) k_aggregate(const float* __restrict__ hprev) {
    int tid = threadIdx.x;
    int warp = tid >> 5, lane = tid & 31;
    int n = blockIdx.x * 8 + warp;
    if (n >= NN) return;

    int grp = lane >> 3;      // edge group 0..3
    int chk = lane & 7;       // float4 chunk 0..7

    const char* hbase = (const char*)hprev;
    const int rowBytes = STRIDE * 4;
    int chunkOff = chk * 16;

    int e0 = d_start[n];
    int len = d_len[n];
    int e1 = e0 + len;
    float4 acc = make_float4(0.f, 0.f, 0.f, 0.f);

    for (int base = e0; base < e1; base += 32) {
        int cnt = e1 - base;
        int ee = base + lane;
        int idx = (ee < e1) ? d_ssrc[ee] : 0;   // pad with node 0 (safe addr)
        if (cnt >= 32) {
            #pragma unroll
            for (int it = 0; it < 8; it++) {
                int s = __shfl_sync(0xffffffffu, idx, it * 4 + grp);
                float4 p = *(const float4*)(hbase + (size_t)s * rowBytes + chunkOff);
                acc.x += p.x; acc.y += p.y; acc.z += p.z; acc.w += p.w;
            }
        } else {
            int nIt = (cnt + 3) >> 2;
            for (int it = 0; it < nIt; it++) {
                int g = it * 4 + grp;
                int s = __shfl_sync(0xffffffffu, idx, g & 31);
                float4 p = *(const float4*)(hbase + (size_t)s * rowBytes + chunkOff);
                if (g < cnt) {
                    acc.x += p.x; acc.y += p.y; acc.z += p.z; acc.w += p.w;
                }
            }
        }
    }
    // reduce the 4 edge-groups: lanes {chk, chk+8, chk+16, chk+24} hold partials
    acc.x += __shfl_xor_sync(0xffffffffu, acc.x, 8);
    acc.y += __shfl_xor_sync(0xffffffffu, acc.y, 8);
    acc.z += __shfl_xor_sync(0xffffffffu, acc.z, 8);
    acc.w += __shfl_xor_sync(0xffffffffu, acc.w, 8);
    acc.x += __shfl_xor_sync(0xffffffffu, acc.x, 16);
    acc.y += __shfl_xor_sync(0xffffffffu, acc.y, 16);
    acc.z += __shfl_xor_sync(0xffffffffu, acc.z, 16);
    acc.w += __shfl_xor_sync(0xffffffffu, acc.w, 16);

    if (lane < 8) {
        float inv = 1.0f / fmaxf((float)len, 1.0f);
        float4 m = make_float4(acc.x * inv, acc.y * inv, acc.z * inv, acc.w * inv);
        *(float4*)(d_mean + (size_t)n * 32 + lane * 4) = m;   // coalesced STG.128
    }
}

// ---------------- dense layer: tanh(x@Ws + mean@Wn + b) -> concat slice --------
#define NPW_D 16
__global__ void __launch_bounds__(256) k_dense(
        const float* __restrict__ x, int xstride,
        float* __restrict__ concat, int layer,
        const float* __restrict__ Ws, const float* __restrict__ Wn,
        const float* __restrict__ b) {
    __shared__ float sWs[1024], sWn[1024], sb[32];
    int tid = threadIdx.x;
    for (int i = tid; i < 1024; i += 256) { sWs[i] = Ws[i]; sWn[i] = Wn[i]; }
    if (tid < 32) sb[tid] = b[tid];
    __syncthreads();

    int warp = tid >> 5, lane = tid & 31;
    float wsr[32], wnr[32];
    #pragma unroll
    for (int k = 0; k < 32; k++) {
        wsr[k] = sWs[k * 32 + lane];
        wnr[k] = sWn[k * 32 + lane];
    }
    float bias = sb[lane];

    int wg = blockIdx.x * 8 + warp;
    int n0 = wg * NPW_D;
    #pragma unroll 1
    for (int i = 0; i < NPW_D; i++) {
        int n = n0 + i;
        if (n >= NN) return;
        const float4* xr = (const float4*)(x + (size_t)n * xstride);
        const float4* mr = (const float4*)(d_mean + (size_t)n * 32);
        float rs = bias, rn = 0.f;
        #pragma unroll
        for (int k4 = 0; k4 < 8; k4++) {
            float4 xv = xr[k4];            // broadcast LDG.128
            float4 mv = mr[k4];            // broadcast LDG.128
            rs += xv.x * wsr[4 * k4]     + xv.y * wsr[4 * k4 + 1]
                + xv.z * wsr[4 * k4 + 2] + xv.w * wsr[4 * k4 + 3];
            rn += mv.x * wnr[4 * k4]     + mv.y * wnr[4 * k4 + 1]
                + mv.z * wnr[4 * k4 + 2] + mv.w * wnr[4 * k4 + 3];
        }
        concat[(size_t)n * 128 + layer * 32 + lane] = tanhf(rs + rn);
    }
}

// ---------------- pair MLP ----------------
__global__ void k_mlp(const float* __restrict__ concat,
                      const int* __restrict__ uidx, const int* __restrict__ iidx,
                      const float* __restrict__ W1, const float* __restrict__ bl1,
                      const float* __restrict__ W2, const float* __restrict__ bl2,
                      float* __restrict__ score, int pairs_per_block) {
    __shared__ float spair[256];
    __shared__ float sred[4];
    int tid = threadIdx.x;   // 0..127
    float w2 = W2[tid];
    float b1 = bl1[tid];
    float b2 = bl2[0];
    int p0 = blockIdx.x * pairs_per_block;
    int p1 = min(NP, p0 + pairs_per_block);
    for (int p = p0; p < p1; p++) {
        int u = uidx[p], it = iidx[p];
        spair[tid]       = concat[(size_t)u  * 128 + tid];
        spair[128 + tid] = concat[(size_t)it * 128 + tid];
        __syncthreads();
        float acc = b1;
        #pragma unroll 8
        for (int k = 0; k < 256; k++) acc += spair[k] * W1[k * 128 + tid];
        float h = fmaxf(acc, 0.f) * w2;
        #pragma unroll
        for (int o = 16; o > 0; o >>= 1) h += __shfl_down_sync(0xffffffffu, h, o);
        if ((tid & 31) == 0) sred[tid >> 5] = h;
        __syncthreads();
        if (tid == 0) {
            float s = sred[0] + sred[1] + sred[2] + sred[3] + b2;
            score[p] = 1.0f / (1.0f + expf(-s));
        }
        __syncthreads();
    }
}

// ---------------- launch ----------------
extern "C" void kernel_launch(void* const* d_in, const int* in_sizes, int n_in,
                              void* d_out, int out_size) {
    const float* x    = (const float*)d_in[0];
    const int*   src  = (const int*)d_in[1];
    const int*   dst  = (const int*)d_in[2];
    const int*   uidx = (const int*)d_in[3];
    const int*   iidx = (const int*)d_in[4];
    const float* Ws[4] = { (const float*)d_in[5], (const float*)d_in[8],
                           (const float*)d_in[11], (const float*)d_in[14] };
    const float* Wn[4] = { (const float*)d_in[6], (const float*)d_in[9],
                           (const float*)d_in[12], (const float*)d_in[15] };
    const float* bb[4] = { (const float*)d_in[7], (const float*)d_in[10],
                           (const float*)d_in[13], (const float*)d_in[16] };
    const float* W1  = (const float*)d_in[17];
    const float* bl1 = (const float*)d_in[18];
    const float* W2  = (const float*)d_in[19];
    const float* bl2 = (const float*)d_in[20];

    float* out    = (float*)d_out;
    float* score  = out;              // output 0: [4096]
    float* concat = out + NP;         // output 1: [200000, 128]

    // CSR build (3 launches; launch index 3 = k_aggregate<32> L0 -> profiled slot)
    k_hist<<<(NE / 4 + 255) / 256, 256>>>(dst);
    k_scan<<<SCAN_NB, SCAN_T>>>();
    k_scatter<<<(NE / 4 + 255) / 256, 256>>>(src, dst);

    // 4 layers: aggregate (gather, high occ) + dense (FFMA, reg weights)
    const int AGG_NBLK = (NN + 7) / 8;
    const int DEN_NBLK = (NN + 8 * NPW_D - 1) / (8 * NPW_D);

    k_aggregate<32><<<AGG_NBLK, 256>>>(x);
    k_dense<<<DEN_NBLK, 256>>>(x, 32, concat, 0, Ws[0], Wn[0], bb[0]);
    for (int L = 1; L < 4; L++) {
        const float* hin = concat + (L - 1) * 32;
        k_aggregate<128><<<AGG_NBLK, 256>>>(hin);
        k_dense<<<DEN_NBLK, 256>>>(hin, 128, concat, L, Ws[L], Wn[L], bb[L]);
    }

    // Pair-scoring MLP.
    const int MLP_BLOCKS = 128;
    k_mlp<<<MLP_BLOCKS, 128>>>(concat, uidx, iidx, W1, bl1, W2, bl2, score,
                               NP / MLP_BLOCKS);
}

// round 13
// speedup vs baseline: 1.0986x; 1.0986x over previous
#include <cuda_runtime.h>
#include <math.h>

#define NN 200000
#define NE 3200000
#define NP 4096
#define SCAN_T 1024
#define SCAN_NB 196   // ceil(NN/1024)

// ---------------- scratch (__device__ globals; no allocation) ----------------
__device__ int d_deg[NN];            // invariant: zero at entry (restored by k_scan)
__device__ int d_start[NN];          // segment start per node (arrival-ordered)
__device__ int d_len[NN];            // segment length per node
__device__ int d_cursor[NN];
__device__ int d_gctr;               // global range allocator (zeroed by k_hist)
__device__ int d_ssrc[NE];           // src indices grouped by dst
__device__ float d_mean[NN * 32];    // per-layer aggregated mean scratch

// ---------------- CSR build: hist -> scan -> scatter (3 launches, scalar) -------
__global__ void k_hist(const int* __restrict__ dst) {
    if (blockIdx.x == 0 && threadIdx.x == 0) d_gctr = 0;   // consumed next launch
    int e = blockIdx.x * blockDim.x + threadIdx.x;
    if (e < NE) atomicAdd(&d_deg[dst[e]], 1);
}

// Block-local inclusive scan + atomic block-range grab (arrival-ordered across
// blocks; valid since consumers only need disjoint start+len per node).
__global__ void k_scan() {
    __shared__ int s[SCAN_T];
    __shared__ int blockBase;
    int t = threadIdx.x;
    int i = blockIdx.x * SCAN_T + t;
    int v = (i < NN) ? d_deg[i] : 0;
    s[t] = v;
    __syncthreads();
    for (int o = 1; o < SCAN_T; o <<= 1) {
        int tv = (t >= o) ? s[t - o] : 0;
        __syncthreads();
        s[t] += tv;
        __syncthreads();
    }
    if (t == SCAN_T - 1) blockBase = atomicAdd(&d_gctr, s[SCAN_T - 1]);
    __syncthreads();
    if (i < NN) {
        int excl = blockBase + s[t] - v;
        d_start[i]  = excl;
        d_cursor[i] = excl;
        d_len[i]    = v;
        d_deg[i]    = 0;                 // restore zero invariant for next call
    }
}

__global__ void k_scatter(const int* __restrict__ src, const int* __restrict__ dst) {
    int e = blockIdx.x * blockDim.x + threadIdx.x;
    if (e < NE) {
        int p = atomicAdd(&d_cursor[dst[e]], 1);
        d_ssrc[p] = src[e];
    }
}

// ---------------- aggregation: mean of in-neighbors -> d_mean ----------------
// One warp per node. Lane = (edge-group l>>3, float4-chunk l&7). Per 32-edge
// chunk we dispatch to a compile-time-unrolled body of exactly nIt=ceil(cnt/4)
// steps (warp-uniform -> no divergence): loads stay batched (MLP=nIt) and the
// typical deg-16 node runs 4 steps instead of a fixed 8.
template <int NIT>
__device__ __forceinline__ void gather_chunk(
        const char* hbase, int rowBytes, int chunkOff,
        int idx, int grp, int cnt, float4& acc) {
    #pragma unroll
    for (int it = 0; it < NIT; it++) {
        int g = it * 4 + grp;
        int s = __shfl_sync(0xffffffffu, idx, g);
        float4 p = make_float4(0.f, 0.f, 0.f, 0.f);
        if (g < cnt)                       // predicated LDG.128
            p = *(const float4*)(hbase + (size_t)s * rowBytes + chunkOff);
        acc.x += p.x; acc.y += p.y; acc.z += p.z; acc.w += p.w;
    }
}

__global__ void __launch_bounds__(256) k_aggregate(
        const float* __restrict__ hprev, int strideFloats) {
    int tid = threadIdx.x;
    int warp = tid >> 5, lane = tid & 31;
    int n = blockIdx.x * 8 + warp;
    if (n >= NN) return;

    int grp = lane >> 3;      // edge group 0..3
    int chk = lane & 7;       // float4 chunk 0..7

    const char* hbase = (const char*)hprev;
    int rowBytes = strideFloats * 4;
    int chunkOff = chk * 16;

    int e0 = d_start[n];
    int len = d_len[n];
    int e1 = e0 + len;
    float4 acc = make_float4(0.f, 0.f, 0.f, 0.f);

    for (int base = e0; base < e1; base += 32) {
        int cnt = e1 - base;                    // 1..32 edges this chunk
        int ee = base + lane;
        int idx = (ee < e1) ? d_ssrc[ee] : 0;
        int nIt = (cnt + 3) >> 2;               // 1..8, warp-uniform
        switch (nIt) {
            case 1: gather_chunk<1>(hbase, rowBytes, chunkOff, idx, grp, cnt, acc); break;
            case 2: gather_chunk<2>(hbase, rowBytes, chunkOff, idx, grp, cnt, acc); break;
            case 3: gather_chunk<3>(hbase, rowBytes, chunkOff, idx, grp, cnt, acc); break;
            case 4: gather_chunk<4>(hbase, rowBytes, chunkOff, idx, grp, cnt, acc); break;
            case 5: gather_chunk<5>(hbase, rowBytes, chunkOff, idx, grp, cnt, acc); break;
            case 6: gather_chunk<6>(hbase, rowBytes, chunkOff, idx, grp, cnt, acc); break;
            case 7: gather_chunk<7>(hbase, rowBytes, chunkOff, idx, grp, cnt, acc); break;
            default: gather_chunk<8>(hbase, rowBytes, chunkOff, idx, grp, cnt, acc); break;
        }
    }
    // reduce the 4 edge-groups: lanes {chk, chk+8, chk+16, chk+24} hold partials
    acc.x += __shfl_xor_sync(0xffffffffu, acc.x, 8);
    acc.y += __shfl_xor_sync(0xffffffffu, acc.y, 8);
    acc.z += __shfl_xor_sync(0xffffffffu, acc.z, 8);
    acc.w += __shfl_xor_sync(0xffffffffu, acc.w, 8);
    acc.x += __shfl_xor_sync(0xffffffffu, acc.x, 16);
    acc.y += __shfl_xor_sync(0xffffffffu, acc.y, 16);
    acc.z += __shfl_xor_sync(0xffffffffu, acc.z, 16);
    acc.w += __shfl_xor_sync(0xffffffffu, acc.w, 16);

    if (lane < 8) {
        float inv = 1.0f / fmaxf((float)len, 1.0f);
        float4 m = make_float4(acc.x * inv, acc.y * inv, acc.z * inv, acc.w * inv);
        *(float4*)(d_mean + (size_t)n * 32 + lane * 4) = m;   // coalesced STG.128
    }
}

// ---------------- dense layer: tanh(x@Ws + mean@Wn + b) -> concat slice --------
#define NPW_D 16
__global__ void __launch_bounds__(256) k_dense(
        const float* __restrict__ x, int xstride,
        float* __restrict__ concat, int layer,
        const float* __restrict__ Ws, const float* __restrict__ Wn,
        const float* __restrict__ b) {
    __shared__ float sWs[1024], sWn[1024], sb[32];
    int tid = threadIdx.x;
    for (int i = tid; i < 1024; i += 256) { sWs[i] = Ws[i]; sWn[i] = Wn[i]; }
    if (tid < 32) sb[tid] = b[tid];
    __syncthreads();

    int warp = tid >> 5, lane = tid & 31;
    float wsr[32], wnr[32];
    #pragma unroll
    for (int k = 0; k < 32; k++) {
        wsr[k] = sWs[k * 32 + lane];
        wnr[k] = sWn[k * 32 + lane];
    }
    float bias = sb[lane];

    int wg = blockIdx.x * 8 + warp;
    int n0 = wg * NPW_D;
    #pragma unroll 1
    for (int i = 0; i < NPW_D; i++) {
        int n = n0 + i;
        if (n >= NN) return;
        const float4* xr = (const float4*)(x + (size_t)n * xstride);
        const float4* mr = (const float4*)(d_mean + (size_t)n * 32);
        float rs = bias, rn = 0.f;
        #pragma unroll
        for (int k4 = 0; k4 < 8; k4++) {
            float4 xv = xr[k4];            // broadcast LDG.128
            float4 mv = mr[k4];            // broadcast LDG.128
            rs += xv.x * wsr[4 * k4]     + xv.y * wsr[4 * k4 + 1]
                + xv.z * wsr[4 * k4 + 2] + xv.w * wsr[4 * k4 + 3];
            rn += mv.x * wnr[4 * k4]     + mv.y * wnr[4 * k4 + 1]
                + mv.z * wnr[4 * k4 + 2] + mv.w * wnr[4 * k4 + 3];
        }
        concat[(size_t)n * 128 + layer * 32 + lane] = tanhf(rs + rn);
    }
}

// ---------------- pair MLP ----------------
__global__ void k_mlp(const float* __restrict__ concat,
                      const int* __restrict__ uidx, const int* __restrict__ iidx,
                      const float* __restrict__ W1, const float* __restrict__ bl1,
                      const float* __restrict__ W2, const float* __restrict__ bl2,
                      float* __restrict__ score, int pairs_per_block) {
    __shared__ float spair[256];
    __shared__ float sred[4];
    int tid = threadIdx.x;   // 0..127
    float w2 = W2[tid];
    float b1 = bl1[tid];
    float b2 = bl2[0];
    int p0 = blockIdx.x * pairs_per_block;
    int p1 = min(NP, p0 + pairs_per_block);
    for (int p = p0; p < p1; p++) {
        int u = uidx[p], it = iidx[p];
        spair[tid]       = concat[(size_t)u  * 128 + tid];
        spair[128 + tid] = concat[(size_t)it * 128 + tid];
        __syncthreads();
        float acc = b1;
        #pragma unroll 8
        for (int k = 0; k < 256; k++) acc += spair[k] * W1[k * 128 + tid];
        float h = fmaxf(acc, 0.f) * w2;
        #pragma unroll
        for (int o = 16; o > 0; o >>= 1) h += __shfl_down_sync(0xffffffffu, h, o);
        if ((tid & 31) == 0) sred[tid >> 5] = h;
        __syncthreads();
        if (tid == 0) {
            float s = sred[0] + sred[1] + sred[2] + sred[3] + b2;
            score[p] = 1.0f / (1.0f + expf(-s));
        }
        __syncthreads();
    }
}

// ---------------- launch ----------------
extern "C" void kernel_launch(void* const* d_in, const int* in_sizes, int n_in,
                              void* d_out, int out_size) {
    const float* x    = (const float*)d_in[0];
    const int*   src  = (const int*)d_in[1];
    const int*   dst  = (const int*)d_in[2];
    const int*   uidx = (const int*)d_in[3];
    const int*   iidx = (const int*)d_in[4];
    const float* Ws[4] = { (const float*)d_in[5], (const float*)d_in[8],
                           (const float*)d_in[11], (const float*)d_in[14] };
    const float* Wn[4] = { (const float*)d_in[6], (const float*)d_in[9],
                           (const float*)d_in[12], (const float*)d_in[15] };
    const float* bb[4] = { (const float*)d_in[7], (const float*)d_in[10],
                           (const float*)d_in[13], (const float*)d_in[16] };
    const float* W1  = (const float*)d_in[17];
    const float* bl1 = (const float*)d_in[18];
    const float* W2  = (const float*)d_in[19];
    const float* bl2 = (const float*)d_in[20];

    float* out    = (float*)d_out;
    float* score  = out;              // output 0: [4096]
    float* concat = out + NP;         // output 1: [200000, 128]

    // CSR build (3 launches; launch index 3 = k_aggregate L0 -> profiled slot)
    k_hist<<<(NE + 255) / 256, 256>>>(dst);
    k_scan<<<SCAN_NB, SCAN_T>>>();
    k_scatter<<<(NE + 255) / 256, 256>>>(src, dst);

    // 4 layers: aggregate (gather, high occ) + dense (FFMA, reg weights)
    const int AGG_NBLK = (NN + 7) / 8;
    const int DEN_NBLK = (NN + 8 * NPW_D - 1) / (8 * NPW_D);

    k_aggregate<<<AGG_NBLK, 256>>>(x, 32);
    k_dense<<<DEN_NBLK, 256>>>(x, 32, concat, 0, Ws[0], Wn[0], bb[0]);
    for (int L = 1; L < 4; L++) {
        const float* hin = concat + (L - 1) * 32;
        k_aggregate<<<AGG_NBLK, 256>>>(hin, 128);
        k_dense<<<DEN_NBLK, 256>>>(hin, 128, concat, L, Ws[L], Wn[L], bb[L]);
    }

    // Pair-scoring MLP.
    const int MLP_BLOCKS = 128;
    k_mlp<<<MLP_BLOCKS, 128>>>(concat, uidx, iidx, W1, bl1, W2, bl2, score,
                               NP / MLP_BLOCKS);
}

// round 14
// speedup vs baseline: 1.2380x; 1.1269x over previous
#include <cuda_runtime.h>
#include <math.h>

#define NN 200000
#define NE 3200000
#define NP 4096
#define SCAN_T 1024
#define SCAN_NB 196   // ceil(NN/1024)
#define NPW_A 4       // nodes per warp in aggregate (NN % (8*NPW_A) == 0)

// ---------------- scratch (__device__ globals; no allocation) ----------------
__device__ int d_deg[NN];            // invariant: zero at entry (restored by k_scan)
__device__ int d_start[NN];          // segment start per node (arrival-ordered)
__device__ int d_len[NN];            // segment length per node
__device__ int d_cursor[NN];
__device__ int d_gctr;               // global range allocator (zeroed by k_hist)
__device__ int d_ssrc[NE];           // src indices grouped by dst
__device__ float d_mean[NN * 32];    // per-layer aggregated mean scratch

__device__ __forceinline__ float tanh_approx(float v) {
    float r;
    asm("tanh.approx.f32 %0, %1;" : "=f"(r) : "f"(v));
    return r;
}

// ---------------- CSR build: hist -> scan -> scatter (3 launches) ----------------
__global__ void k_hist(const int* __restrict__ dst) {
    if (blockIdx.x == 0 && threadIdx.x == 0) d_gctr = 0;   // consumed next launch
    int e = blockIdx.x * blockDim.x + threadIdx.x;
    if (e < NE) atomicAdd(&d_deg[dst[e]], 1);
}

// Block-local inclusive scan + atomic block-range grab (arrival-ordered across
// blocks; valid since consumers only need disjoint start+len per node).
__global__ void k_scan() {
    __shared__ int s[SCAN_T];
    __shared__ int blockBase;
    int t = threadIdx.x;
    int i = blockIdx.x * SCAN_T + t;
    int v = (i < NN) ? d_deg[i] : 0;
    s[t] = v;
    __syncthreads();
    for (int o = 1; o < SCAN_T; o <<= 1) {
        int tv = (t >= o) ? s[t - o] : 0;
        __syncthreads();
        s[t] += tv;
        __syncthreads();
    }
    if (t == SCAN_T - 1) blockBase = atomicAdd(&d_gctr, s[SCAN_T - 1]);
    __syncthreads();
    if (i < NN) {
        int excl = blockBase + s[t] - v;
        d_start[i]  = excl;
        d_cursor[i] = excl;
        d_len[i]    = v;
        d_deg[i]    = 0;                 // restore zero invariant for next call
    }
}

__global__ void k_scatter(const int* __restrict__ src, const int* __restrict__ dst) {
    int e = blockIdx.x * blockDim.x + threadIdx.x;
    if (e < NE) {
        int p = atomicAdd(&d_cursor[dst[e]], 1);
        d_ssrc[p] = src[e];
    }
}

// ---------------- aggregation: mean of in-neighbors -> d_mean ----------------
// 4 nodes per warp, software-pipelined: node i+1's index chunk is in flight
// while node i's features are gathered (overlaps the two dependent L2 trips).
// Per chunk: dispatch to a compile-time-unrolled body of nIt=ceil(cnt/4) steps
// (warp-uniform), loads batched (MLP=nIt), predicated LDG.128.
template <int NIT>
__device__ __forceinline__ void gather_chunk(
        const char* hbase, int rowBytes, int chunkOff,
        int idx, int grp, int cnt, float4& acc) {
    #pragma unroll
    for (int it = 0; it < NIT; it++) {
        int g = it * 4 + grp;
        int s = __shfl_sync(0xffffffffu, idx, g);
        float4 p = make_float4(0.f, 0.f, 0.f, 0.f);
        if (g < cnt)                       // predicated LDG.128
            p = *(const float4*)(hbase + (size_t)s * rowBytes + chunkOff);
        acc.x += p.x; acc.y += p.y; acc.z += p.z; acc.w += p.w;
    }
}

__device__ __forceinline__ void gather_dispatch(
        const char* hbase, int rowBytes, int chunkOff,
        int idx, int grp, int cnt, float4& acc) {
    int nIt = (cnt + 3) >> 2;              // 1..8, warp-uniform
    switch (nIt) {
        case 1: gather_chunk<1>(hbase, rowBytes, chunkOff, idx, grp, cnt, acc); break;
        case 2: gather_chunk<2>(hbase, rowBytes, chunkOff, idx, grp, cnt, acc); break;
        case 3: gather_chunk<3>(hbase, rowBytes, chunkOff, idx, grp, cnt, acc); break;
        case 4: gather_chunk<4>(hbase, rowBytes, chunkOff, idx, grp, cnt, acc); break;
        case 5: gather_chunk<5>(hbase, rowBytes, chunkOff, idx, grp, cnt, acc); break;
        case 6: gather_chunk<6>(hbase, rowBytes, chunkOff, idx, grp, cnt, acc); break;
        case 7: gather_chunk<7>(hbase, rowBytes, chunkOff, idx, grp, cnt, acc); break;
        default: gather_chunk<8>(hbase, rowBytes, chunkOff, idx, grp, cnt, acc); break;
    }
}

__global__ void __launch_bounds__(256) k_aggregate(
        const float* __restrict__ hprev, int strideFloats) {
    int tid = threadIdx.x;
    int warp = tid >> 5, lane = tid & 31;
    int n0 = (blockIdx.x * 8 + warp) * NPW_A;     // exact: NN % 32 == 0

    int grp = lane >> 3;      // edge group 0..3
    int chk = lane & 7;       // float4 chunk 0..7

    const char* hbase = (const char*)hprev;
    int rowBytes = strideFloats * 4;
    int chunkOff = chk * 16;

    // coalesced metadata for the 4 nodes (lanes 0..3)
    int m_st = (lane < NPW_A) ? d_start[n0 + lane] : 0;
    int m_ln = (lane < NPW_A) ? d_len[n0 + lane] : 0;

    // prefetch chunk-0 indices of node 0
    int st_n = __shfl_sync(0xffffffffu, m_st, 0);
    int ln_n = __shfl_sync(0xffffffffu, m_ln, 0);
    int idx_next = (lane < ln_n) ? d_ssrc[st_n + lane] : 0;

    #pragma unroll
    for (int i = 0; i < NPW_A; i++) {
        int st = st_n, ln = ln_n;
        int idx_cur = idx_next;
        if (i + 1 < NPW_A) {
            st_n = __shfl_sync(0xffffffffu, m_st, i + 1);
            ln_n = __shfl_sync(0xffffffffu, m_ln, i + 1);
            idx_next = (lane < ln_n) ? d_ssrc[st_n + lane] : 0;   // in flight during gather
        }

        float4 acc = make_float4(0.f, 0.f, 0.f, 0.f);
        int cnt0 = min(ln, 32);
        if (cnt0 > 0)
            gather_dispatch(hbase, rowBytes, chunkOff, idx_cur, grp, cnt0, acc);
        // rare tail: degree > 32
        for (int base = st + 32; base < st + ln; base += 32) {
            int cnt = st + ln - base;
            int ee = base + lane;
            int idx = (ee < st + ln) ? d_ssrc[ee] : 0;
            gather_dispatch(hbase, rowBytes, chunkOff, idx, grp, cnt, acc);
        }

        // reduce the 4 edge-groups: lanes {chk, chk+8, chk+16, chk+24} hold partials
        acc.x += __shfl_xor_sync(0xffffffffu, acc.x, 8);
        acc.y += __shfl_xor_sync(0xffffffffu, acc.y, 8);
        acc.z += __shfl_xor_sync(0xffffffffu, acc.z, 8);
        acc.w += __shfl_xor_sync(0xffffffffu, acc.w, 8);
        acc.x += __shfl_xor_sync(0xffffffffu, acc.x, 16);
        acc.y += __shfl_xor_sync(0xffffffffu, acc.y, 16);
        acc.z += __shfl_xor_sync(0xffffffffu, acc.z, 16);
        acc.w += __shfl_xor_sync(0xffffffffu, acc.w, 16);

        if (lane < 8) {
            float inv = 1.0f / fmaxf((float)ln, 1.0f);
            float4 m = make_float4(acc.x * inv, acc.y * inv, acc.z * inv, acc.w * inv);
            *(float4*)(d_mean + (size_t)(n0 + i) * 32 + lane * 4) = m;
        }
    }
}

// ---------------- dense layer: tanh(x@Ws + mean@Wn + b) -> concat slice --------
#define NPW_D 16
__global__ void __launch_bounds__(256) k_dense(
        const float* __restrict__ x, int xstride,
        float* __restrict__ concat, int layer,
        const float* __restrict__ Ws, const float* __restrict__ Wn,
        const float* __restrict__ b) {
    __shared__ float sWs[1024], sWn[1024], sb[32];
    int tid = threadIdx.x;
    for (int i = tid; i < 1024; i += 256) { sWs[i] = Ws[i]; sWn[i] = Wn[i]; }
    if (tid < 32) sb[tid] = b[tid];
    __syncthreads();

    int warp = tid >> 5, lane = tid & 31;
    float wsr[32], wnr[32];
    #pragma unroll
    for (int k = 0; k < 32; k++) {
        wsr[k] = sWs[k * 32 + lane];
        wnr[k] = sWn[k * 32 + lane];
    }
    float bias = sb[lane];

    int wg = blockIdx.x * 8 + warp;
    int n0 = wg * NPW_D;
    #pragma unroll 1
    for (int i = 0; i < NPW_D; i++) {
        int n = n0 + i;
        if (n >= NN) return;
        const float4* xr = (const float4*)(x + (size_t)n * xstride);
        const float4* mr = (const float4*)(d_mean + (size_t)n * 32);
        float rs = bias, rn = 0.f;
        #pragma unroll
        for (int k4 = 0; k4 < 8; k4++) {
            float4 xv = xr[k4];            // broadcast LDG.128
            float4 mv = mr[k4];            // broadcast LDG.128
            rs += xv.x * wsr[4 * k4]     + xv.y * wsr[4 * k4 + 1]
                + xv.z * wsr[4 * k4 + 2] + xv.w * wsr[4 * k4 + 3];
            rn += mv.x * wnr[4 * k4]     + mv.y * wnr[4 * k4 + 1]
                + mv.z * wnr[4 * k4 + 2] + mv.w * wnr[4 * k4 + 3];
        }
        concat[(size_t)n * 128 + layer * 32 + lane] = tanh_approx(rs + rn);
    }
}

// ---------------- pair MLP ----------------
__global__ void k_mlp(const float* __restrict__ concat,
                      const int* __restrict__ uidx, const int* __restrict__ iidx,
                      const float* __restrict__ W1, const float* __restrict__ bl1,
                      const float* __restrict__ W2, const float* __restrict__ bl2,
                      float* __restrict__ score, int pairs_per_block) {
    __shared__ float spair[256];
    __shared__ float sred[4];
    int tid = threadIdx.x;   // 0..127
    float w2 = W2[tid];
    float b1 = bl1[tid];
    float b2 = bl2[0];
    int p0 = blockIdx.x * pairs_per_block;
    int p1 = min(NP, p0 + pairs_per_block);
    for (int p = p0; p < p1; p++) {
        int u = uidx[p], it = iidx[p];
        spair[tid]       = concat[(size_t)u  * 128 + tid];
        spair[128 + tid] = concat[(size_t)it * 128 + tid];
        __syncthreads();
        float acc = b1;
        #pragma unroll 8
        for (int k = 0; k < 256; k++) acc += spair[k] * W1[k * 128 + tid];
        float h = fmaxf(acc, 0.f) * w2;
        #pragma unroll
        for (int o = 16; o > 0; o >>= 1) h += __shfl_down_sync(0xffffffffu, h, o);
        if ((tid & 31) == 0) sred[tid >> 5] = h;
        __syncthreads();
        if (tid == 0) {
            float s = sred[0] + sred[1] + sred[2] + sred[3] + b2;
            score[p] = 1.0f / (1.0f + expf(-s));
        }
        __syncthreads();
    }
}

// ---------------- launch ----------------
extern "C" void kernel_launch(void* const* d_in, const int* in_sizes, int n_in,
                              void* d_out, int out_size) {
    const float* x    = (const float*)d_in[0];
    const int*   src  = (const int*)d_in[1];
    const int*   dst  = (const int*)d_in[2];
    const int*   uidx = (const int*)d_in[3];
    const int*   iidx = (const int*)d_in[4];
    const float* Ws[4] = { (const float*)d_in[5], (const float*)d_in[8],
                           (const float*)d_in[11], (const float*)d_in[14] };
    const float* Wn[4] = { (const float*)d_in[6], (const float*)d_in[9],
                           (const float*)d_in[12], (const float*)d_in[15] };
    const float* bb[4] = { (const float*)d_in[7], (const float*)d_in[10],
                           (const float*)d_in[13], (const float*)d_in[16] };
    const float* W1  = (const float*)d_in[17];
    const float* bl1 = (const float*)d_in[18];
    const float* W2  = (const float*)d_in[19];
    const float* bl2 = (const float*)d_in[20];

    float* out    = (float*)d_out;
    float* score  = out;              // output 0: [4096]
    float* concat = out + NP;         // output 1: [200000, 128]

    // CSR build (3 launches; launch index 3 = k_aggregate L0 -> profiled slot)
    k_hist<<<(NE + 255) / 256, 256>>>(dst);
    k_scan<<<SCAN_NB, SCAN_T>>>();
    k_scatter<<<(NE + 255) / 256, 256>>>(src, dst);

    // 4 layers: aggregate (pipelined gather) + dense (FFMA, reg weights)
    const int AGG_NBLK = NN / (8 * NPW_A);        // 6250, exact
    const int DEN_NBLK = (NN + 8 * NPW_D - 1) / (8 * NPW_D);

    k_aggregate<<<AGG_NBLK, 256>>>(x, 32);
    k_dense<<<DEN_NBLK, 256>>>(x, 32, concat, 0, Ws[0], Wn[0], bb[0]);
    for (int L = 1; L < 4; L++) {
        const float* hin = concat + (L - 1) * 32;
        k_aggregate<<<AGG_NBLK, 256>>>(hin, 128);
        k_dense<<<DEN_NBLK, 256>>>(hin, 128, concat, L, Ws[L], Wn[L], bb[L]);
    }

    // Pair-scoring MLP.
    const int MLP_BLOCKS = 128;
    k_mlp<<<MLP_BLOCKS, 128>>>(concat, uidx, iidx, W1, bl1, W2, bl2, score,
                               NP / MLP_BLOCKS);
}